// round 11
// baseline (speedup 1.0000x reference)
#include <cuda_runtime.h>
#include <cuda_fp16.h>
#include <cstdint>
#include <math.h>

#define N_ROWS 8192
#define DIMK   1024
#define NCTA3  444            // 3 CTAs per SM
#define NJOBS_T 2080          // triangle 128x128 tiles incl. diagonal: 64*65/2
#define STAGE_BYTES 32768u

// ---------------- scratch (static device memory, no allocs) ----------------
__device__ __align__(16) __half g_Xh[N_ROWS * DIMK];   // 16 MB fp16 row-major
__device__ float g_rnorm[N_ROWS];                      // 1/max(||x||,eps)
__device__ unsigned long long g_best[N_ROWS];          // packed (enc(val)<<32 | ~col)
__device__ float g_logd[N_ROWS];
__device__ int   g_done = 0;                           // dist-block ticket counter

// ---------------- helpers ----------------
__device__ __forceinline__ uint32_t smem_u32(const void* p) {
    uint32_t a;
    asm("{ .reg .u64 t; cvta.to.shared.u64 t, %1; cvt.u32.u64 %0, t; }" : "=r"(a) : "l"(p));
    return a;
}
__device__ __forceinline__ void cp16(uint32_t dst, const void* src) {
    asm volatile("cp.async.cg.shared.global [%0], [%1], 16;" :: "r"(dst), "l"(src));
}
__device__ __forceinline__ void ldsm4(uint32_t& r0, uint32_t& r1, uint32_t& r2, uint32_t& r3,
                                      uint32_t addr) {
    asm volatile("ldmatrix.sync.aligned.m8n8.x4.shared.b16 {%0,%1,%2,%3}, [%4];"
                 : "=r"(r0), "=r"(r1), "=r"(r2), "=r"(r3) : "r"(addr));
}
__device__ __forceinline__ void mma16816h(uint32_t* c, uint32_t a0, uint32_t a1, uint32_t a2,
                                          uint32_t a3, uint32_t b0, uint32_t b1) {
    asm volatile("mma.sync.aligned.m16n8k16.row.col.f16.f16.f16.f16 "
                 "{%0,%1}, {%2,%3,%4,%5}, {%6,%7}, {%0,%1};"
                 : "+r"(c[0]), "+r"(c[1])
                 : "r"(a0), "r"(a1), "r"(a2), "r"(a3), "r"(b0), "r"(b1));
}
// monotonic float->u32 (total order preserved, incl. negatives)
__device__ __forceinline__ uint32_t fenc(float v) {
    const uint32_t u = __float_as_uint(v);
    return (u & 0x80000000u) ? ~u : (u | 0x80000000u);
}
// job index -> (rb, cb) over the 64x64 block triangle (cb >= rb).
// Row rb has (64 - rb) jobs; cumulative S(r) = r*(129-r)/2.
__device__ __forceinline__ uint32_t job_decode(int jj) {
    int u = 0;
    #pragma unroll 1
    while ((u + 1) * (129 - (u + 1)) / 2 <= jj) u++;
    const int c = u + (jj - u * (129 - u) / 2);
    return ((uint32_t)u << 8) | (uint32_t)c;
}

// ---------------- kernel 1: row norms + fp16 pack; reset g_best ----------------
__global__ void koleo_normalize_kernel(const float* __restrict__ x) {
    const int row = blockIdx.x;
    const int tid = threadIdx.x;  // 256 threads, 4 elems each
    if (tid == 0) g_best[row] = 0ull;
    const float4 v = ((const float4*)(x + (size_t)row * DIMK))[tid];
    float ss = v.x * v.x + v.y * v.y + v.z * v.z + v.w * v.w;
    #pragma unroll
    for (int o = 16; o; o >>= 1) ss += __shfl_xor_sync(0xFFFFFFFFu, ss, o);
    __shared__ float ws[9];
    if ((tid & 31) == 0) ws[tid >> 5] = ss;
    __syncthreads();
    if (tid == 0) {
        float t = 0.f;
        #pragma unroll
        for (int i = 0; i < 8; i++) t += ws[i];
        const float r = 1.f / fmaxf(sqrtf(t), 1e-8f);
        ws[8] = r;
        g_rnorm[row] = r;
    }
    __syncthreads();
    const float s = ws[8];
    __half2 h0 = __floats2half2_rn(v.x * s, v.y * s);
    __half2 h1 = __floats2half2_rn(v.z * s, v.w * s);
    uint2 u;
    u.x = *(const uint32_t*)&h0;
    u.y = *(const uint32_t*)&h1;
    *(uint2*)(g_Xh + (size_t)row * DIMK + tid * 4) = u;
}

// ---------------- kernel 2: persistent fp16 GEMM over the block triangle ----------------
// (unchanged from R10: 444 CTAs / 3 per SM, tile 128x128, warp tile 64x32,
//  K64 stages, 2 smem buffers, depth-1 cp.async, dual-side argmax folds)

__device__ __forceinline__ void copy_stream(uint32_t sbase, const uint32_t* jtab,
                                            int s, int S, int tid) {
    if (s < S) {
        const uint32_t rbcb = jtab[s >> 4];
        const int rb = (int)(rbcb >> 8), cb = (int)(rbcb & 255u), kc = s & 15;
        const uint32_t dst = sbase + (uint32_t)(s & 1) * STAGE_BYTES;
        const __half* gA = g_Xh + (size_t)(rb * 128) * DIMK + kc * 64;
        const __half* gB = g_Xh + (size_t)(cb * 128) * DIMK + kc * 64;
        #pragma unroll
        for (int i = 0; i < 4; i++) {
            const int idx = tid + i * 256;
            const int r = idx >> 3, ch = idx & 7;
            const uint32_t doff = (uint32_t)r * 128u + ((uint32_t)(ch ^ (r & 7)) << 4);
            cp16(dst + doff, gA + (size_t)r * DIMK + ch * 8);
        }
        #pragma unroll
        for (int i = 0; i < 4; i++) {
            const int idx = tid + i * 256;
            const int r = idx >> 3, ch = idx & 7;
            const uint32_t doff = (uint32_t)r * 128u + ((uint32_t)(ch ^ (r & 7)) << 4);
            cp16(dst + 16384u + doff, gB + (size_t)r * DIMK + ch * 8);
        }
    }
    asm volatile("cp.async.commit_group;" ::: "memory");
}

__global__ void __launch_bounds__(256, 3) koleo_argmax_kernel() {
    extern __shared__ unsigned char smem[];
    const uint32_t sbase = smem_u32(smem);
    uint32_t* jtab = (uint32_t*)(smem + 2 * STAGE_BYTES);
    const int tid = threadIdx.x;
    const int lane = tid & 31;
    const int wid = tid >> 5;
    const int wm = wid & 1;        // rows [wm*64, wm*64+64)
    const int wn = wid >> 1;       // cols [wn*32, wn*32+32)
    const int cta = blockIdx.x;
    const int m = (NJOBS_T - cta + NCTA3 - 1) / NCTA3;   // jobs for this CTA (<=5)
    const int S = m * 16;

    if (tid < 8 && tid < m) jtab[tid] = job_decode(cta + tid * NCTA3);
    __syncthreads();

    uint32_t c2[4][4][2];   // fp16x2 accumulators (warp tile 64x32)
    #pragma unroll
    for (int a = 0; a < 4; a++)
        #pragma unroll
        for (int b = 0; b < 4; b++) { c2[a][b][0] = 0u; c2[a][b][1] = 0u; }

    copy_stream(sbase, jtab, 0, S, tid);

    for (int s = 0; s < S; s++) {
        asm volatile("cp.async.wait_group 0;" ::: "memory");
        __syncthreads();
        copy_stream(sbase, jtab, s + 1, S, tid);   // overlaps compute(s)

        const uint32_t A = sbase + (uint32_t)(s & 1) * STAGE_BYTES;
        const uint32_t B = A + 16384u;

        #pragma unroll
        for (int t = 0; t < 4; t++) {
            const uint32_t kc = (uint32_t)(t << 1) + (uint32_t)(lane >> 4);
            uint32_t bf[2][4], af[4][4];
            #pragma unroll
            for (int nb = 0; nb < 2; nb++) {
                const uint32_t r = (uint32_t)(wn * 32 + nb * 16 + (lane & 15));
                const uint32_t addr = B + r * 128u + ((kc ^ (r & 7u)) << 4);
                ldsm4(bf[nb][0], bf[nb][1], bf[nb][2], bf[nb][3], addr);
            }
            #pragma unroll
            for (int mt = 0; mt < 4; mt++) {
                const uint32_t r = (uint32_t)(wm * 64 + mt * 16 + (lane & 15));
                const uint32_t addr = A + r * 128u + ((kc ^ (r & 7u)) << 4);
                ldsm4(af[mt][0], af[mt][1], af[mt][2], af[mt][3], addr);
            }
            #pragma unroll
            for (int mt = 0; mt < 4; mt++)
                #pragma unroll
                for (int j = 0; j < 4; j++)
                    mma16816h(c2[mt][j], af[mt][0], af[mt][1], af[mt][2], af[mt][3],
                              bf[j >> 1][j & 1], bf[j >> 1][2 + (j & 1)]);
        }

        if ((s & 15) == 15) {
            const uint32_t rbcb = jtab[s >> 4];
            const int rb = (int)(rbcb >> 8), cb = (int)(rbcb & 255u);
            const int colb = cb * 128 + wn * 32;
            const int rowb = rb * 128 + wm * 64;

            // ---- column-side fold (symmetry): per-column max over 128 rows ----
            #pragma unroll
            for (int j = 0; j < 4; j++) {
                #pragma unroll
                for (int h = 0; h < 2; h++) {
                    const int gcol = colb + j * 8 + (lane & 3) * 2 + h;
                    float cv = -2.f; int cr = 0;
                    #pragma unroll
                    for (int mt = 0; mt < 4; mt++) {
                        #pragma unroll
                        for (int rh = 0; rh < 2; rh++) {
                            const __half2 hv = *(const __half2*)&c2[mt][j][rh];
                            const float v = h ? __high2float(hv) : __low2float(hv);
                            const int grow = rowb + mt * 16 + (lane >> 2) + rh * 8;
                            if (grow != gcol && (v > cv || (v == cv && grow < cr))) {
                                cv = v; cr = grow;
                            }
                        }
                    }
                    unsigned long long key =
                        ((unsigned long long)fenc(cv) << 32) |
                        (unsigned long long)(0xFFFFFFFFu - (uint32_t)cr);
                    #pragma unroll
                    for (int o = 4; o <= 16; o <<= 1) {
                        const unsigned long long ok = __shfl_xor_sync(0xFFFFFFFFu, key, o);
                        if (ok > key) key = ok;
                    }
                    if (lane < 4) atomicMax(&g_best[gcol], key);
                }
            }

            // ---- row-side fold + accumulator reset ----
            #pragma unroll
            for (int mt = 0; mt < 4; mt++) {
                #pragma unroll
                for (int rh = 0; rh < 2; rh++) {
                    const int grow = rowb + mt * 16 + (lane >> 2) + rh * 8;
                    float bv = -2.f; int bi = 0;
                    #pragma unroll
                    for (int j = 0; j < 4; j++) {
                        const __half2 hv = *(const __half2*)&c2[mt][j][rh];
                        const float v0 = __low2float(hv);
                        const float v1 = __high2float(hv);
                        const int col0 = colb + j * 8 + (lane & 3) * 2;
                        if (col0 != grow && v0 > bv) { bv = v0; bi = col0; }
                        if (col0 + 1 != grow && v1 > bv) { bv = v1; bi = col0 + 1; }
                        c2[mt][j][rh] = 0u;
                    }
                    unsigned long long key =
                        ((unsigned long long)fenc(bv) << 32) |
                        (unsigned long long)(0xFFFFFFFFu - (uint32_t)bi);
                    #pragma unroll
                    for (int o = 1; o <= 2; o <<= 1) {
                        const unsigned long long ok = __shfl_xor_sync(0xFFFFFFFFu, key, o);
                        if (ok > key) key = ok;
                    }
                    if ((lane & 3) == 0) atomicMax(&g_best[grow], key);
                }
            }
        }
    }
}

// ---------------- kernel 3: exact fp32 distance + fused deterministic finish ----------------
__global__ void koleo_dist_kernel(const float* __restrict__ x, float* __restrict__ out) {
    const int i = blockIdx.x;
    const int tid = threadIdx.x;  // 128
    const int j = (int)(0xFFFFFFFFu - (uint32_t)g_best[i]);
    const float ri = g_rnorm[i], rj = g_rnorm[j];
    const float4* a = (const float4*)(x + (size_t)i * DIMK);
    const float4* b = (const float4*)(x + (size_t)j * DIMK);
    float s = 0.f;
    #pragma unroll
    for (int t = 0; t < 2; t++) {
        const int idx = tid + t * 128;
        const float4 av = a[idx], bv = b[idx];
        const float d0 = av.x * ri - bv.x * rj + 1e-8f;
        const float d1 = av.y * ri - bv.y * rj + 1e-8f;
        const float d2 = av.z * ri - bv.z * rj + 1e-8f;
        const float d3 = av.w * ri - bv.w * rj + 1e-8f;
        s += d0 * d0 + d1 * d1 + d2 * d2 + d3 * d3;
    }
    #pragma unroll
    for (int o = 16; o; o >>= 1) s += __shfl_xor_sync(0xFFFFFFFFu, s, o);
    __shared__ float ws[4];
    __shared__ int last;
    if ((tid & 31) == 0) ws[tid >> 5] = s;
    __syncthreads();
    if (tid == 0) {
        const float t = ws[0] + ws[1] + ws[2] + ws[3];
        g_logd[i] = logf(sqrtf(t) + 1e-8f);
        __threadfence();
        const int ticket = atomicAdd(&g_done, 1);
        last = (ticket == N_ROWS - 1) ? 1 : 0;
    }
    __syncthreads();
    if (last) {
        // last block: all prior g_logd writes are visible (fence+ticket). Fixed-order sum.
        __threadfence();
        float s2 = 0.f;
        #pragma unroll 1
        for (int k = tid; k < N_ROWS; k += 128) s2 += g_logd[k];
        #pragma unroll
        for (int o = 16; o; o >>= 1) s2 += __shfl_xor_sync(0xFFFFFFFFu, s2, o);
        __shared__ float fs[4];
        if ((tid & 31) == 0) fs[tid >> 5] = s2;
        __syncthreads();
        if (tid == 0) {
            out[0] = -((fs[0] + fs[1] + fs[2] + fs[3]) / 8192.f);
            g_done = 0;   // reset for graph replay
        }
    }
}

// ---------------- launch ----------------
extern "C" void kernel_launch(void* const* d_in, const int* in_sizes, int n_in,
                              void* d_out, int out_size) {
    (void)in_sizes; (void)n_in; (void)out_size;
    const float* x = (const float*)d_in[0];
    const int smem_bytes = 2 * 32768 + 64;
    cudaFuncSetAttribute(koleo_argmax_kernel, cudaFuncAttributeMaxDynamicSharedMemorySize,
                         smem_bytes);
    koleo_normalize_kernel<<<N_ROWS, 256>>>(x);
    koleo_argmax_kernel<<<NCTA3, 256, smem_bytes>>>();
    koleo_dist_kernel<<<N_ROWS, 128>>>(x, (float*)d_out);
}

// round 12
// speedup vs baseline: 1.1142x; 1.1142x over previous
#include <cuda_runtime.h>
#include <cuda_fp16.h>
#include <cstdint>
#include <math.h>

#define N_ROWS 8192
#define DIMK   1024
#define NCTA3  444            // 3 CTAs per SM
#define NJOBS_T 2080          // triangle 128x128 tiles incl. diagonal: 64*65/2
#define STAGE_BYTES 32768u
#define JSENT 0xFFFFFFFFu

// ---------------- scratch (static device memory, no allocs) ----------------
__device__ __align__(16) float  g_Xn[N_ROWS * DIMK];   // 32 MB normalized fp32
__device__ __align__(16) __half g_Xh[N_ROWS * DIMK];   // 16 MB fp16 row-major
__device__ unsigned long long g_best[N_ROWS];          // packed (enc(val)<<32 | ~col)
__device__ float g_logd[N_ROWS];
__device__ int   g_jobctr;                             // dynamic work queue head

// ---------------- helpers ----------------
__device__ __forceinline__ uint32_t smem_u32(const void* p) {
    uint32_t a;
    asm("{ .reg .u64 t; cvta.to.shared.u64 t, %1; cvt.u32.u64 %0, t; }" : "=r"(a) : "l"(p));
    return a;
}
__device__ __forceinline__ void cp16(uint32_t dst, const void* src) {
    asm volatile("cp.async.cg.shared.global [%0], [%1], 16;" :: "r"(dst), "l"(src));
}
__device__ __forceinline__ void ldsm4(uint32_t& r0, uint32_t& r1, uint32_t& r2, uint32_t& r3,
                                      uint32_t addr) {
    asm volatile("ldmatrix.sync.aligned.m8n8.x4.shared.b16 {%0,%1,%2,%3}, [%4];"
                 : "=r"(r0), "=r"(r1), "=r"(r2), "=r"(r3) : "r"(addr));
}
__device__ __forceinline__ void mma16816h(uint32_t* c, uint32_t a0, uint32_t a1, uint32_t a2,
                                          uint32_t a3, uint32_t b0, uint32_t b1) {
    asm volatile("mma.sync.aligned.m16n8k16.row.col.f16.f16.f16.f16 "
                 "{%0,%1}, {%2,%3,%4,%5}, {%6,%7}, {%0,%1};"
                 : "+r"(c[0]), "+r"(c[1])
                 : "r"(a0), "r"(a1), "r"(a2), "r"(a3), "r"(b0), "r"(b1));
}
// monotonic float->u32 (total order preserved, incl. negatives)
__device__ __forceinline__ uint32_t fenc(float v) {
    const uint32_t u = __float_as_uint(v);
    return (u & 0x80000000u) ? ~u : (u | 0x80000000u);
}
// job index -> (rb, cb) over the 64x64 block triangle (cb >= rb).
// Row rb has (64 - rb) jobs; cumulative S(r) = r*(129-r)/2.
__device__ __forceinline__ uint32_t job_decode(int jj) {
    int u = 0;
    #pragma unroll 1
    while ((u + 1) * (129 - (u + 1)) / 2 <= jj) u++;
    const int c = u + (jj - u * (129 - u) / 2);
    return ((uint32_t)u << 8) | (uint32_t)c;
}

// ---------------- kernel 1: normalize rows, write fp32 + fp16; reset g_best, g_jobctr ----
__global__ void koleo_normalize_kernel(const float* __restrict__ x) {
    const int row = blockIdx.x;
    const int tid = threadIdx.x;  // 256 threads, 4 elems each
    if (tid == 0) {
        g_best[row] = 0ull;
        if (row == 0) g_jobctr = 0;
    }
    const float4 v = ((const float4*)(x + (size_t)row * DIMK))[tid];
    float ss = v.x * v.x + v.y * v.y + v.z * v.z + v.w * v.w;
    #pragma unroll
    for (int o = 16; o; o >>= 1) ss += __shfl_xor_sync(0xFFFFFFFFu, ss, o);
    __shared__ float ws[9];
    if ((tid & 31) == 0) ws[tid >> 5] = ss;
    __syncthreads();
    if (tid == 0) {
        float t = 0.f;
        #pragma unroll
        for (int i = 0; i < 8; i++) t += ws[i];
        ws[8] = 1.f / fmaxf(sqrtf(t), 1e-8f);
    }
    __syncthreads();
    const float s = ws[8];
    float4 y; y.x = v.x * s; y.y = v.y * s; y.z = v.z * s; y.w = v.w * s;
    ((float4*)(g_Xn + (size_t)row * DIMK))[tid] = y;

    __half2 h0 = __floats2half2_rn(y.x, y.y);
    __half2 h1 = __floats2half2_rn(y.z, y.w);
    uint2 u;
    u.x = *(const uint32_t*)&h0;
    u.y = *(const uint32_t*)&h1;
    *(uint2*)(g_Xh + (size_t)row * DIMK + tid * 4) = u;
}

// ---------------- kernel 2: persistent fp16 GEMM, dynamic job queue ----------------
// 444 CTAs (3/SM). Jobs pulled from g_jobctr; rolling 8-entry jtab in smem,
// refilled one stage before each job boundary so the cp.async stream never drains.
// Tile 128x128, warp tile 64x32, K64 stages, 2 smem buffers, depth-1 prefetch.

__device__ __forceinline__ void copy_stream(uint32_t sbase, const uint32_t* jtab,
                                            int s, int tid) {
    const uint32_t rbcb = jtab[(s >> 4) & 7];
    if (rbcb != JSENT) {
        const int rb = (int)(rbcb >> 8), cb = (int)(rbcb & 255u), kc = s & 15;
        const uint32_t dst = sbase + (uint32_t)(s & 1) * STAGE_BYTES;
        const __half* gA = g_Xh + (size_t)(rb * 128) * DIMK + kc * 64;
        const __half* gB = g_Xh + (size_t)(cb * 128) * DIMK + kc * 64;
        #pragma unroll
        for (int i = 0; i < 4; i++) {
            const int idx = tid + i * 256;
            const int r = idx >> 3, ch = idx & 7;
            const uint32_t doff = (uint32_t)r * 128u + ((uint32_t)(ch ^ (r & 7)) << 4);
            cp16(dst + doff, gA + (size_t)r * DIMK + ch * 8);
        }
        #pragma unroll
        for (int i = 0; i < 4; i++) {
            const int idx = tid + i * 256;
            const int r = idx >> 3, ch = idx & 7;
            const uint32_t doff = (uint32_t)r * 128u + ((uint32_t)(ch ^ (r & 7)) << 4);
            cp16(dst + 16384u + doff, gB + (size_t)r * DIMK + ch * 8);
        }
    }
    asm volatile("cp.async.commit_group;" ::: "memory");
}

__global__ void __launch_bounds__(256, 3) koleo_argmax_kernel() {
    extern __shared__ unsigned char smem[];
    const uint32_t sbase = smem_u32(smem);
    uint32_t* jtab = (uint32_t*)(smem + 2 * STAGE_BYTES);   // rolling ring of 8 job ids
    const int tid = threadIdx.x;
    const int lane = tid & 31;
    const int wid = tid >> 5;
    const int wm = wid & 1;        // rows [wm*64, wm*64+64)
    const int wn = wid >> 1;       // cols [wn*32, wn*32+32)

    if (tid == 0) {
        const int j0 = atomicAdd(&g_jobctr, 1);
        jtab[0] = (j0 < NJOBS_T) ? job_decode(j0) : JSENT;
    }
    __syncthreads();

    uint32_t c2[4][4][2];   // fp16x2 accumulators (warp tile 64x32)
    #pragma unroll
    for (int a = 0; a < 4; a++)
        #pragma unroll
        for (int b = 0; b < 4; b++) { c2[a][b][0] = 0u; c2[a][b][1] = 0u; }

    copy_stream(sbase, jtab, 0, tid);

    for (int s = 0;; s++) {
        asm volatile("cp.async.wait_group 0;" ::: "memory");
        __syncthreads();
        const uint32_t curj = jtab[(s >> 4) & 7];
        if (curj == JSENT) break;
        // fetch the NEXT job one stage before the boundary; published by next sync
        if ((s & 15) == 14 && tid == 0) {
            const int jn = atomicAdd(&g_jobctr, 1);
            jtab[((s >> 4) + 1) & 7] = (jn < NJOBS_T) ? job_decode(jn) : JSENT;
        }
        copy_stream(sbase, jtab, s + 1, tid);   // overlaps compute(s)

        const uint32_t A = sbase + (uint32_t)(s & 1) * STAGE_BYTES;
        const uint32_t B = A + 16384u;

        #pragma unroll
        for (int t = 0; t < 4; t++) {
            const uint32_t kc = (uint32_t)(t << 1) + (uint32_t)(lane >> 4);
            uint32_t bf[2][4], af[4][4];
            #pragma unroll
            for (int nb = 0; nb < 2; nb++) {
                const uint32_t r = (uint32_t)(wn * 32 + nb * 16 + (lane & 15));
                const uint32_t addr = B + r * 128u + ((kc ^ (r & 7u)) << 4);
                ldsm4(bf[nb][0], bf[nb][1], bf[nb][2], bf[nb][3], addr);
            }
            #pragma unroll
            for (int mt = 0; mt < 4; mt++) {
                const uint32_t r = (uint32_t)(wm * 64 + mt * 16 + (lane & 15));
                const uint32_t addr = A + r * 128u + ((kc ^ (r & 7u)) << 4);
                ldsm4(af[mt][0], af[mt][1], af[mt][2], af[mt][3], addr);
            }
            #pragma unroll
            for (int mt = 0; mt < 4; mt++)
                #pragma unroll
                for (int j = 0; j < 4; j++)
                    mma16816h(c2[mt][j], af[mt][0], af[mt][1], af[mt][2], af[mt][3],
                              bf[j >> 1][j & 1], bf[j >> 1][2 + (j & 1)]);
        }

        if ((s & 15) == 15) {
            const int rb = (int)(curj >> 8), cb = (int)(curj & 255u);
            const int colb = cb * 128 + wn * 32;
            const int rowb = rb * 128 + wm * 64;

            // ---- column-side fold (symmetry): per-column max over 128 rows ----
            #pragma unroll
            for (int j = 0; j < 4; j++) {
                #pragma unroll
                for (int h = 0; h < 2; h++) {
                    const int gcol = colb + j * 8 + (lane & 3) * 2 + h;
                    float cv = -2.f; int cr = 0;
                    #pragma unroll
                    for (int mt = 0; mt < 4; mt++) {
                        #pragma unroll
                        for (int rh = 0; rh < 2; rh++) {
                            const __half2 hv = *(const __half2*)&c2[mt][j][rh];
                            const float v = h ? __high2float(hv) : __low2float(hv);
                            const int grow = rowb + mt * 16 + (lane >> 2) + rh * 8;
                            if (grow != gcol && (v > cv || (v == cv && grow < cr))) {
                                cv = v; cr = grow;
                            }
                        }
                    }
                    unsigned long long key =
                        ((unsigned long long)fenc(cv) << 32) |
                        (unsigned long long)(0xFFFFFFFFu - (uint32_t)cr);
                    #pragma unroll
                    for (int o = 4; o <= 16; o <<= 1) {
                        const unsigned long long ok = __shfl_xor_sync(0xFFFFFFFFu, key, o);
                        if (ok > key) key = ok;
                    }
                    if (lane < 4) atomicMax(&g_best[gcol], key);
                }
            }

            // ---- row-side fold + accumulator reset ----
            #pragma unroll
            for (int mt = 0; mt < 4; mt++) {
                #pragma unroll
                for (int rh = 0; rh < 2; rh++) {
                    const int grow = rowb + mt * 16 + (lane >> 2) + rh * 8;
                    float bv = -2.f; int bi = 0;
                    #pragma unroll
                    for (int j = 0; j < 4; j++) {
                        const __half2 hv = *(const __half2*)&c2[mt][j][rh];
                        const float v0 = __low2float(hv);
                        const float v1 = __high2float(hv);
                        const int col0 = colb + j * 8 + (lane & 3) * 2;
                        if (col0 != grow && v0 > bv) { bv = v0; bi = col0; }
                        if (col0 + 1 != grow && v1 > bv) { bv = v1; bi = col0 + 1; }
                        c2[mt][j][rh] = 0u;
                    }
                    unsigned long long key =
                        ((unsigned long long)fenc(bv) << 32) |
                        (unsigned long long)(0xFFFFFFFFu - (uint32_t)bi);
                    #pragma unroll
                    for (int o = 1; o <= 2; o <<= 1) {
                        const unsigned long long ok = __shfl_xor_sync(0xFFFFFFFFu, key, o);
                        if (ok > key) key = ok;
                    }
                    if ((lane & 3) == 0) atomicMax(&g_best[grow], key);
                }
            }
        }
    }
}

// ---------------- kernel 3: exact fp32 distance to argmax neighbor ----------------
__global__ void koleo_dist_kernel() {
    const int i = blockIdx.x;
    const int tid = threadIdx.x;  // 128
    const int j = (int)(0xFFFFFFFFu - (uint32_t)g_best[i]);
    const float4* a = (const float4*)(g_Xn + (size_t)i * DIMK);
    const float4* b = (const float4*)(g_Xn + (size_t)j * DIMK);
    float s = 0.f;
    #pragma unroll
    for (int t = 0; t < 2; t++) {
        const int idx = tid + t * 128;
        const float4 av = a[idx], bv = b[idx];
        const float d0 = av.x - bv.x + 1e-8f;
        const float d1 = av.y - bv.y + 1e-8f;
        const float d2 = av.z - bv.z + 1e-8f;
        const float d3 = av.w - bv.w + 1e-8f;
        s += d0 * d0 + d1 * d1 + d2 * d2 + d3 * d3;
    }
    #pragma unroll
    for (int o = 16; o; o >>= 1) s += __shfl_xor_sync(0xFFFFFFFFu, s, o);
    __shared__ float ws[4];
    if ((tid & 31) == 0) ws[tid >> 5] = s;
    __syncthreads();
    if (tid == 0) {
        const float t = ws[0] + ws[1] + ws[2] + ws[3];
        g_logd[i] = logf(sqrtf(t) + 1e-8f);
    }
}

// ---------------- kernel 4: deterministic mean reduction ----------------
__global__ void koleo_finish_kernel(float* __restrict__ out) {
    const int tid = threadIdx.x;  // 1024
    float s = 0.f;
    #pragma unroll
    for (int t = 0; t < 8; t++) s += g_logd[tid + t * 1024];
    #pragma unroll
    for (int o = 16; o; o >>= 1) s += __shfl_xor_sync(0xFFFFFFFFu, s, o);
    __shared__ float ws[32];
    if ((tid & 31) == 0) ws[tid >> 5] = s;
    __syncthreads();
    if (tid == 0) {
        float t = 0.f;
        #pragma unroll
        for (int i = 0; i < 32; i++) t += ws[i];
        out[0] = -(t / 8192.f);
    }
}

// ---------------- launch ----------------
extern "C" void kernel_launch(void* const* d_in, const int* in_sizes, int n_in,
                              void* d_out, int out_size) {
    (void)in_sizes; (void)n_in; (void)out_size;
    const float* x = (const float*)d_in[0];
    const int smem_bytes = 2 * 32768 + 64;
    cudaFuncSetAttribute(koleo_argmax_kernel, cudaFuncAttributeMaxDynamicSharedMemorySize,
                         smem_bytes);
    koleo_normalize_kernel<<<N_ROWS, 256>>>(x);
    koleo_argmax_kernel<<<NCTA3, 256, smem_bytes>>>();
    koleo_dist_kernel<<<N_ROWS, 128>>>();
    koleo_finish_kernel<<<1, 1024>>>((float*)d_out);
}

// round 13
// speedup vs baseline: 1.1336x; 1.0174x over previous
#include <cuda_runtime.h>
#include <cuda_fp16.h>
#include <cstdint>
#include <math.h>

#define N_ROWS 8192
#define DIMK   1024
#define NCTA3  444            // 3 CTAs per SM
#define NJOBS_T 2080          // triangle 128x128 tiles incl. diagonal: 64*65/2
#define STAGE_BYTES 32768u
#define JSENT 0xFFFFFFFFu

// ---------------- scratch (static device memory, no allocs) ----------------
__device__ __align__(16) __half g_Xh[N_ROWS * DIMK];   // 16 MB fp16 row-major
__device__ float g_rnorm[N_ROWS];                      // 1/max(||x||,eps)
__device__ unsigned long long g_best[N_ROWS];          // packed (enc(val)<<32 | ~col)
__device__ float g_logd[N_ROWS];
__device__ int   g_jobctr;                             // dynamic work queue head

// ---------------- helpers ----------------
__device__ __forceinline__ uint32_t smem_u32(const void* p) {
    uint32_t a;
    asm("{ .reg .u64 t; cvta.to.shared.u64 t, %1; cvt.u32.u64 %0, t; }" : "=r"(a) : "l"(p));
    return a;
}
__device__ __forceinline__ void cp16(uint32_t dst, const void* src) {
    asm volatile("cp.async.cg.shared.global [%0], [%1], 16;" :: "r"(dst), "l"(src));
}
__device__ __forceinline__ void ldsm4(uint32_t& r0, uint32_t& r1, uint32_t& r2, uint32_t& r3,
                                      uint32_t addr) {
    asm volatile("ldmatrix.sync.aligned.m8n8.x4.shared.b16 {%0,%1,%2,%3}, [%4];"
                 : "=r"(r0), "=r"(r1), "=r"(r2), "=r"(r3) : "r"(addr));
}
__device__ __forceinline__ void mma16816h(uint32_t* c, uint32_t a0, uint32_t a1, uint32_t a2,
                                          uint32_t a3, uint32_t b0, uint32_t b1) {
    asm volatile("mma.sync.aligned.m16n8k16.row.col.f16.f16.f16.f16 "
                 "{%0,%1}, {%2,%3,%4,%5}, {%6,%7}, {%0,%1};"
                 : "+r"(c[0]), "+r"(c[1])
                 : "r"(a0), "r"(a1), "r"(a2), "r"(a3), "r"(b0), "r"(b1));
}
// monotonic float->u32 (total order preserved, incl. negatives)
__device__ __forceinline__ uint32_t fenc(float v) {
    const uint32_t u = __float_as_uint(v);
    return (u & 0x80000000u) ? ~u : (u | 0x80000000u);
}
// job index -> (rb, cb) over the 64x64 block triangle (cb >= rb).
// Row rb has (64 - rb) jobs; cumulative S(r) = r*(129-r)/2.
__device__ __forceinline__ uint32_t job_decode(int jj) {
    int u = 0;
    #pragma unroll 1
    while ((u + 1) * (129 - (u + 1)) / 2 <= jj) u++;
    const int c = u + (jj - u * (129 - u) / 2);
    return ((uint32_t)u << 8) | (uint32_t)c;
}

// ---------------- kernel 1: row norms + fp16 pack; reset g_best, g_jobctr ----------------
__global__ void koleo_normalize_kernel(const float* __restrict__ x) {
    const int row = blockIdx.x;
    const int tid = threadIdx.x;  // 256 threads, 4 elems each
    if (tid == 0) {
        g_best[row] = 0ull;
        if (row == 0) g_jobctr = 0;
    }
    const float4 v = ((const float4*)(x + (size_t)row * DIMK))[tid];
    float ss = v.x * v.x + v.y * v.y + v.z * v.z + v.w * v.w;
    #pragma unroll
    for (int o = 16; o; o >>= 1) ss += __shfl_xor_sync(0xFFFFFFFFu, ss, o);
    __shared__ float ws[9];
    if ((tid & 31) == 0) ws[tid >> 5] = ss;
    __syncthreads();
    if (tid == 0) {
        float t = 0.f;
        #pragma unroll
        for (int i = 0; i < 8; i++) t += ws[i];
        const float r = 1.f / fmaxf(sqrtf(t), 1e-8f);
        ws[8] = r;
        g_rnorm[row] = r;
    }
    __syncthreads();
    const float s = ws[8];
    __half2 h0 = __floats2half2_rn(v.x * s, v.y * s);
    __half2 h1 = __floats2half2_rn(v.z * s, v.w * s);
    uint2 u;
    u.x = *(const uint32_t*)&h0;
    u.y = *(const uint32_t*)&h1;
    *(uint2*)(g_Xh + (size_t)row * DIMK + tid * 4) = u;
}

// ---------------- kernel 2: persistent fp16 GEMM, dynamic job queue (R12, unchanged) ----
// 444 CTAs (3/SM). Jobs pulled from g_jobctr; rolling 8-entry jtab in smem,
// refilled one stage before each job boundary so the cp.async stream never drains.
// Tile 128x128, warp tile 64x32, K64 stages, 2 smem buffers, depth-1 prefetch.

__device__ __forceinline__ void copy_stream(uint32_t sbase, const uint32_t* jtab,
                                            int s, int tid) {
    const uint32_t rbcb = jtab[(s >> 4) & 7];
    if (rbcb != JSENT) {
        const int rb = (int)(rbcb >> 8), cb = (int)(rbcb & 255u), kc = s & 15;
        const uint32_t dst = sbase + (uint32_t)(s & 1) * STAGE_BYTES;
        const __half* gA = g_Xh + (size_t)(rb * 128) * DIMK + kc * 64;
        const __half* gB = g_Xh + (size_t)(cb * 128) * DIMK + kc * 64;
        #pragma unroll
        for (int i = 0; i < 4; i++) {
            const int idx = tid + i * 256;
            const int r = idx >> 3, ch = idx & 7;
            const uint32_t doff = (uint32_t)r * 128u + ((uint32_t)(ch ^ (r & 7)) << 4);
            cp16(dst + doff, gA + (size_t)r * DIMK + ch * 8);
        }
        #pragma unroll
        for (int i = 0; i < 4; i++) {
            const int idx = tid + i * 256;
            const int r = idx >> 3, ch = idx & 7;
            const uint32_t doff = (uint32_t)r * 128u + ((uint32_t)(ch ^ (r & 7)) << 4);
            cp16(dst + 16384u + doff, gB + (size_t)r * DIMK + ch * 8);
        }
    }
    asm volatile("cp.async.commit_group;" ::: "memory");
}

__global__ void __launch_bounds__(256, 3) koleo_argmax_kernel() {
    extern __shared__ unsigned char smem[];
    const uint32_t sbase = smem_u32(smem);
    uint32_t* jtab = (uint32_t*)(smem + 2 * STAGE_BYTES);   // rolling ring of 8 job ids
    const int tid = threadIdx.x;
    const int lane = tid & 31;
    const int wid = tid >> 5;
    const int wm = wid & 1;        // rows [wm*64, wm*64+64)
    const int wn = wid >> 1;       // cols [wn*32, wn*32+32)

    if (tid == 0) {
        const int j0 = atomicAdd(&g_jobctr, 1);
        jtab[0] = (j0 < NJOBS_T) ? job_decode(j0) : JSENT;
    }
    __syncthreads();

    uint32_t c2[4][4][2];   // fp16x2 accumulators (warp tile 64x32)
    #pragma unroll
    for (int a = 0; a < 4; a++)
        #pragma unroll
        for (int b = 0; b < 4; b++) { c2[a][b][0] = 0u; c2[a][b][1] = 0u; }

    copy_stream(sbase, jtab, 0, tid);

    for (int s = 0;; s++) {
        asm volatile("cp.async.wait_group 0;" ::: "memory");
        __syncthreads();
        const uint32_t curj = jtab[(s >> 4) & 7];
        if (curj == JSENT) break;
        // fetch the NEXT job one stage before the boundary; published by next sync
        if ((s & 15) == 14 && tid == 0) {
            const int jn = atomicAdd(&g_jobctr, 1);
            jtab[((s >> 4) + 1) & 7] = (jn < NJOBS_T) ? job_decode(jn) : JSENT;
        }
        copy_stream(sbase, jtab, s + 1, tid);   // overlaps compute(s)

        const uint32_t A = sbase + (uint32_t)(s & 1) * STAGE_BYTES;
        const uint32_t B = A + 16384u;

        #pragma unroll
        for (int t = 0; t < 4; t++) {
            const uint32_t kc = (uint32_t)(t << 1) + (uint32_t)(lane >> 4);
            uint32_t bf[2][4], af[4][4];
            #pragma unroll
            for (int nb = 0; nb < 2; nb++) {
                const uint32_t r = (uint32_t)(wn * 32 + nb * 16 + (lane & 15));
                const uint32_t addr = B + r * 128u + ((kc ^ (r & 7u)) << 4);
                ldsm4(bf[nb][0], bf[nb][1], bf[nb][2], bf[nb][3], addr);
            }
            #pragma unroll
            for (int mt = 0; mt < 4; mt++) {
                const uint32_t r = (uint32_t)(wm * 64 + mt * 16 + (lane & 15));
                const uint32_t addr = A + r * 128u + ((kc ^ (r & 7u)) << 4);
                ldsm4(af[mt][0], af[mt][1], af[mt][2], af[mt][3], addr);
            }
            #pragma unroll
            for (int mt = 0; mt < 4; mt++)
                #pragma unroll
                for (int j = 0; j < 4; j++)
                    mma16816h(c2[mt][j], af[mt][0], af[mt][1], af[mt][2], af[mt][3],
                              bf[j >> 1][j & 1], bf[j >> 1][2 + (j & 1)]);
        }

        if ((s & 15) == 15) {
            const int rb = (int)(curj >> 8), cb = (int)(curj & 255u);
            const int colb = cb * 128 + wn * 32;
            const int rowb = rb * 128 + wm * 64;

            // ---- column-side fold (symmetry): per-column max over 128 rows ----
            #pragma unroll
            for (int j = 0; j < 4; j++) {
                #pragma unroll
                for (int h = 0; h < 2; h++) {
                    const int gcol = colb + j * 8 + (lane & 3) * 2 + h;
                    float cv = -2.f; int cr = 0;
                    #pragma unroll
                    for (int mt = 0; mt < 4; mt++) {
                        #pragma unroll
                        for (int rh = 0; rh < 2; rh++) {
                            const __half2 hv = *(const __half2*)&c2[mt][j][rh];
                            const float v = h ? __high2float(hv) : __low2float(hv);
                            const int grow = rowb + mt * 16 + (lane >> 2) + rh * 8;
                            if (grow != gcol && (v > cv || (v == cv && grow < cr))) {
                                cv = v; cr = grow;
                            }
                        }
                    }
                    unsigned long long key =
                        ((unsigned long long)fenc(cv) << 32) |
                        (unsigned long long)(0xFFFFFFFFu - (uint32_t)cr);
                    #pragma unroll
                    for (int o = 4; o <= 16; o <<= 1) {
                        const unsigned long long ok = __shfl_xor_sync(0xFFFFFFFFu, key, o);
                        if (ok > key) key = ok;
                    }
                    if (lane < 4) atomicMax(&g_best[gcol], key);
                }
            }

            // ---- row-side fold + accumulator reset ----
            #pragma unroll
            for (int mt = 0; mt < 4; mt++) {
                #pragma unroll
                for (int rh = 0; rh < 2; rh++) {
                    const int grow = rowb + mt * 16 + (lane >> 2) + rh * 8;
                    float bv = -2.f; int bi = 0;
                    #pragma unroll
                    for (int j = 0; j < 4; j++) {
                        const __half2 hv = *(const __half2*)&c2[mt][j][rh];
                        const float v0 = __low2float(hv);
                        const float v1 = __high2float(hv);
                        const int col0 = colb + j * 8 + (lane & 3) * 2;
                        if (col0 != grow && v0 > bv) { bv = v0; bi = col0; }
                        if (col0 + 1 != grow && v1 > bv) { bv = v1; bi = col0 + 1; }
                        c2[mt][j][rh] = 0u;
                    }
                    unsigned long long key =
                        ((unsigned long long)fenc(bv) << 32) |
                        (unsigned long long)(0xFFFFFFFFu - (uint32_t)bi);
                    #pragma unroll
                    for (int o = 1; o <= 2; o <<= 1) {
                        const unsigned long long ok = __shfl_xor_sync(0xFFFFFFFFu, key, o);
                        if (ok > key) key = ok;
                    }
                    if ((lane & 3) == 0) atomicMax(&g_best[grow], key);
                }
            }
        }
    }
}

// ---------------- kernel 3: exact fp32 distance from input + row norms ----------------
__global__ void koleo_dist_kernel(const float* __restrict__ x) {
    const int i = blockIdx.x;
    const int tid = threadIdx.x;  // 128
    const int j = (int)(0xFFFFFFFFu - (uint32_t)g_best[i]);
    const float ri = g_rnorm[i], rj = g_rnorm[j];
    const float4* a = (const float4*)(x + (size_t)i * DIMK);
    const float4* b = (const float4*)(x + (size_t)j * DIMK);
    float s = 0.f;
    #pragma unroll
    for (int t = 0; t < 2; t++) {
        const int idx = tid + t * 128;
        const float4 av = a[idx], bv = b[idx];
        const float d0 = av.x * ri - bv.x * rj + 1e-8f;
        const float d1 = av.y * ri - bv.y * rj + 1e-8f;
        const float d2 = av.z * ri - bv.z * rj + 1e-8f;
        const float d3 = av.w * ri - bv.w * rj + 1e-8f;
        s += d0 * d0 + d1 * d1 + d2 * d2 + d3 * d3;
    }
    #pragma unroll
    for (int o = 16; o; o >>= 1) s += __shfl_xor_sync(0xFFFFFFFFu, s, o);
    __shared__ float ws[4];
    if ((tid & 31) == 0) ws[tid >> 5] = s;
    __syncthreads();
    if (tid == 0) {
        const float t = ws[0] + ws[1] + ws[2] + ws[3];
        g_logd[i] = logf(sqrtf(t) + 1e-8f);
    }
}

// ---------------- kernel 4: deterministic mean reduction (R12, unchanged) ----------------
__global__ void koleo_finish_kernel(float* __restrict__ out) {
    const int tid = threadIdx.x;  // 1024
    float s = 0.f;
    #pragma unroll
    for (int t = 0; t < 8; t++) s += g_logd[tid + t * 1024];
    #pragma unroll
    for (int o = 16; o; o >>= 1) s += __shfl_xor_sync(0xFFFFFFFFu, s, o);
    __shared__ float ws[32];
    if ((tid & 31) == 0) ws[tid >> 5] = s;
    __syncthreads();
    if (tid == 0) {
        float t = 0.f;
        #pragma unroll
        for (int i = 0; i < 32; i++) t += ws[i];
        out[0] = -(t / 8192.f);
    }
}

// ---------------- launch ----------------
extern "C" void kernel_launch(void* const* d_in, const int* in_sizes, int n_in,
                              void* d_out, int out_size) {
    (void)in_sizes; (void)n_in; (void)out_size;
    const float* x = (const float*)d_in[0];
    const int smem_bytes = 2 * 32768 + 64;
    cudaFuncSetAttribute(koleo_argmax_kernel, cudaFuncAttributeMaxDynamicSharedMemorySize,
                         smem_bytes);
    koleo_normalize_kernel<<<N_ROWS, 256>>>(x);
    koleo_argmax_kernel<<<NCTA3, 256, smem_bytes>>>();
    koleo_dist_kernel<<<N_ROWS, 128>>>(x);
    koleo_finish_kernel<<<1, 1024>>>((float*)d_out);
}

// round 14
// speedup vs baseline: 1.1601x; 1.0234x over previous
#include <cuda_runtime.h>
#include <cuda_fp16.h>
#include <cstdint>
#include <math.h>

#define N_ROWS 8192
#define DIMK   1024
#define NCTA3  444            // 3 CTAs per SM
#define NJOBS_T 2080          // triangle 128x128 tiles incl. diagonal: 64*65/2
#define STAGE_BYTES 32768u
#define JSENT 0xFFFFFFFFu

// ---------------- scratch (static device memory, no allocs) ----------------
__device__ __align__(16) __half g_Xh[N_ROWS * DIMK];   // 16 MB fp16 row-major
__device__ float g_rnorm[N_ROWS];                      // 1/max(||x||,eps)
__device__ unsigned long long g_best[N_ROWS];          // packed (enc(val)<<32 | ~col)
__device__ float g_logd[N_ROWS];
__device__ int   g_jobctr;                             // dynamic work queue head

// ---------------- helpers ----------------
__device__ __forceinline__ uint32_t smem_u32(const void* p) {
    uint32_t a;
    asm("{ .reg .u64 t; cvta.to.shared.u64 t, %1; cvt.u32.u64 %0, t; }" : "=r"(a) : "l"(p));
    return a;
}
__device__ __forceinline__ void cp16(uint32_t dst, const void* src) {
    asm volatile("cp.async.cg.shared.global [%0], [%1], 16;" :: "r"(dst), "l"(src));
}
__device__ __forceinline__ void ldsm4(uint32_t& r0, uint32_t& r1, uint32_t& r2, uint32_t& r3,
                                      uint32_t addr) {
    asm volatile("ldmatrix.sync.aligned.m8n8.x4.shared.b16 {%0,%1,%2,%3}, [%4];"
                 : "=r"(r0), "=r"(r1), "=r"(r2), "=r"(r3) : "r"(addr));
}
__device__ __forceinline__ void mma16816h(uint32_t* c, uint32_t a0, uint32_t a1, uint32_t a2,
                                          uint32_t a3, uint32_t b0, uint32_t b1) {
    asm volatile("mma.sync.aligned.m16n8k16.row.col.f16.f16.f16.f16 "
                 "{%0,%1}, {%2,%3,%4,%5}, {%6,%7}, {%0,%1};"
                 : "+r"(c[0]), "+r"(c[1])
                 : "r"(a0), "r"(a1), "r"(a2), "r"(a3), "r"(b0), "r"(b1));
}
// monotonic float->u32 (total order preserved, incl. negatives)
__device__ __forceinline__ uint32_t fenc(float v) {
    const uint32_t u = __float_as_uint(v);
    return (u & 0x80000000u) ? ~u : (u | 0x80000000u);
}
// job index -> (rb, cb) over the 64x64 block triangle (cb >= rb).
// Row rb has (64 - rb) jobs; cumulative S(r) = r*(129-r)/2.
__device__ __forceinline__ uint32_t job_decode(int jj) {
    int u = 0;
    #pragma unroll 1
    while ((u + 1) * (129 - (u + 1)) / 2 <= jj) u++;
    const int c = u + (jj - u * (129 - u) / 2);
    return ((uint32_t)u << 8) | (uint32_t)c;
}

// ---------------- kernel 1: row norms + fp16 pack; reset g_best, g_jobctr ----------------
__global__ void koleo_normalize_kernel(const float* __restrict__ x) {
    const int row = blockIdx.x;
    const int tid = threadIdx.x;  // 256 threads, 4 elems each
    if (tid == 0) {
        g_best[row] = 0ull;
        if (row == 0) g_jobctr = 0;
    }
    const float4 v = ((const float4*)(x + (size_t)row * DIMK))[tid];
    float ss = v.x * v.x + v.y * v.y + v.z * v.z + v.w * v.w;
    #pragma unroll
    for (int o = 16; o; o >>= 1) ss += __shfl_xor_sync(0xFFFFFFFFu, ss, o);
    __shared__ float ws[9];
    if ((tid & 31) == 0) ws[tid >> 5] = ss;
    __syncthreads();
    if (tid == 0) {
        float t = 0.f;
        #pragma unroll
        for (int i = 0; i < 8; i++) t += ws[i];
        const float r = 1.f / fmaxf(sqrtf(t), 1e-8f);
        ws[8] = r;
        g_rnorm[row] = r;
    }
    __syncthreads();
    const float s = ws[8];
    __half2 h0 = __floats2half2_rn(v.x * s, v.y * s);
    __half2 h1 = __floats2half2_rn(v.z * s, v.w * s);
    uint2 u;
    u.x = *(const uint32_t*)&h0;
    u.y = *(const uint32_t*)&h1;
    *(uint2*)(g_Xh + (size_t)row * DIMK + tid * 4) = u;
}

// ---------------- kernel 2: persistent fp16 GEMM, dynamic job queue ----------------
// 444 CTAs (3/SM). Jobs pulled from g_jobctr; rolling 8-entry jtab in smem.
// Tile 128x128, warp tile 64x32, K64 stages, 2 smem buffers, depth-1 prefetch.
// Stage-head reorder: kstep-0 ldmatrix issued BEFORE next-stage copy so the
// tensor pipe refills while cp.async/address ALU issue in the MMA shadow.

__device__ __forceinline__ void copy_stream(uint32_t sbase, const uint32_t* jtab,
                                            int s, int tid) {
    const uint32_t rbcb = jtab[(s >> 4) & 7];
    if (rbcb != JSENT) {
        const int rb = (int)(rbcb >> 8), cb = (int)(rbcb & 255u), kc = s & 15;
        const uint32_t dst = sbase + (uint32_t)(s & 1) * STAGE_BYTES;
        const __half* gA = g_Xh + (size_t)(rb * 128) * DIMK + kc * 64;
        const __half* gB = g_Xh + (size_t)(cb * 128) * DIMK + kc * 64;
        #pragma unroll
        for (int i = 0; i < 4; i++) {
            const int idx = tid + i * 256;
            const int r = idx >> 3, ch = idx & 7;
            const uint32_t doff = (uint32_t)r * 128u + ((uint32_t)(ch ^ (r & 7)) << 4);
            cp16(dst + doff, gA + (size_t)r * DIMK + ch * 8);
        }
        #pragma unroll
        for (int i = 0; i < 4; i++) {
            const int idx = tid + i * 256;
            const int r = idx >> 3, ch = idx & 7;
            const uint32_t doff = (uint32_t)r * 128u + ((uint32_t)(ch ^ (r & 7)) << 4);
            cp16(dst + 16384u + doff, gB + (size_t)r * DIMK + ch * 8);
        }
    }
    asm volatile("cp.async.commit_group;" ::: "memory");
}

__global__ void __launch_bounds__(256, 3) koleo_argmax_kernel() {
    extern __shared__ unsigned char smem[];
    const uint32_t sbase = smem_u32(smem);
    uint32_t* jtab = (uint32_t*)(smem + 2 * STAGE_BYTES);   // rolling ring of 8 job ids
    const int tid = threadIdx.x;
    const int lane = tid & 31;
    const int wid = tid >> 5;
    const int wm = wid & 1;        // rows [wm*64, wm*64+64)
    const int wn = wid >> 1;       // cols [wn*32, wn*32+32)

    if (tid == 0) {
        const int j0 = atomicAdd(&g_jobctr, 1);
        jtab[0] = (j0 < NJOBS_T) ? job_decode(j0) : JSENT;
    }
    __syncthreads();

    uint32_t c2[4][4][2];   // fp16x2 accumulators (warp tile 64x32)
    #pragma unroll
    for (int a = 0; a < 4; a++)
        #pragma unroll
        for (int b = 0; b < 4; b++) { c2[a][b][0] = 0u; c2[a][b][1] = 0u; }

    copy_stream(sbase, jtab, 0, tid);

    for (int s = 0;; s++) {
        asm volatile("cp.async.wait_group 0;" ::: "memory");
        __syncthreads();
        const uint32_t curj = jtab[(s >> 4) & 7];
        if (curj == JSENT) break;

        const uint32_t A = sbase + (uint32_t)(s & 1) * STAGE_BYTES;
        const uint32_t B = A + 16384u;

        // ---- kstep 0 fragment loads FIRST (fills the tensor-pipe pipeline) ----
        uint32_t bf[2][4], af[4][4];
        {
            const uint32_t kc = (uint32_t)(lane >> 4);
            #pragma unroll
            for (int nb = 0; nb < 2; nb++) {
                const uint32_t r = (uint32_t)(wn * 32 + nb * 16 + (lane & 15));
                ldsm4(bf[nb][0], bf[nb][1], bf[nb][2], bf[nb][3],
                      B + r * 128u + ((kc ^ (r & 7u)) << 4));
            }
            #pragma unroll
            for (int mt = 0; mt < 4; mt++) {
                const uint32_t r = (uint32_t)(wm * 64 + mt * 16 + (lane & 15));
                ldsm4(af[mt][0], af[mt][1], af[mt][2], af[mt][3],
                      A + r * 128u + ((kc ^ (r & 7u)) << 4));
            }
        }

        // ---- next-job fetch + next-stage copy issue in the LDSM/MMA shadow ----
        if ((s & 15) == 14 && tid == 0) {
            const int jn = atomicAdd(&g_jobctr, 1);
            jtab[((s >> 4) + 1) & 7] = (jn < NJOBS_T) ? job_decode(jn) : JSENT;
        }
        copy_stream(sbase, jtab, s + 1, tid);

        // ---- kstep 0 MMAs ----
        #pragma unroll
        for (int mt = 0; mt < 4; mt++)
            #pragma unroll
            for (int j = 0; j < 4; j++)
                mma16816h(c2[mt][j], af[mt][0], af[mt][1], af[mt][2], af[mt][3],
                          bf[j >> 1][j & 1], bf[j >> 1][2 + (j & 1)]);

        // ---- ksteps 1..3 ----
        #pragma unroll
        for (int t = 1; t < 4; t++) {
            const uint32_t kc = (uint32_t)(t << 1) + (uint32_t)(lane >> 4);
            #pragma unroll
            for (int nb = 0; nb < 2; nb++) {
                const uint32_t r = (uint32_t)(wn * 32 + nb * 16 + (lane & 15));
                ldsm4(bf[nb][0], bf[nb][1], bf[nb][2], bf[nb][3],
                      B + r * 128u + ((kc ^ (r & 7u)) << 4));
            }
            #pragma unroll
            for (int mt = 0; mt < 4; mt++) {
                const uint32_t r = (uint32_t)(wm * 64 + mt * 16 + (lane & 15));
                ldsm4(af[mt][0], af[mt][1], af[mt][2], af[mt][3],
                      A + r * 128u + ((kc ^ (r & 7u)) << 4));
            }
            #pragma unroll
            for (int mt = 0; mt < 4; mt++)
                #pragma unroll
                for (int j = 0; j < 4; j++)
                    mma16816h(c2[mt][j], af[mt][0], af[mt][1], af[mt][2], af[mt][3],
                              bf[j >> 1][j & 1], bf[j >> 1][2 + (j & 1)]);
        }

        if ((s & 15) == 15) {
            const int rb = (int)(curj >> 8), cb = (int)(curj & 255u);
            const int colb = cb * 128 + wn * 32;
            const int rowb = rb * 128 + wm * 64;

            // ---- column-side fold (symmetry): per-column max over 128 rows ----
            #pragma unroll
            for (int j = 0; j < 4; j++) {
                #pragma unroll
                for (int h = 0; h < 2; h++) {
                    const int gcol = colb + j * 8 + (lane & 3) * 2 + h;
                    float cv = -2.f; int cr = 0;
                    #pragma unroll
                    for (int mt = 0; mt < 4; mt++) {
                        #pragma unroll
                        for (int rh = 0; rh < 2; rh++) {
                            const __half2 hv = *(const __half2*)&c2[mt][j][rh];
                            const float v = h ? __high2float(hv) : __low2float(hv);
                            const int grow = rowb + mt * 16 + (lane >> 2) + rh * 8;
                            if (grow != gcol && (v > cv || (v == cv && grow < cr))) {
                                cv = v; cr = grow;
                            }
                        }
                    }
                    unsigned long long key =
                        ((unsigned long long)fenc(cv) << 32) |
                        (unsigned long long)(0xFFFFFFFFu - (uint32_t)cr);
                    #pragma unroll
                    for (int o = 4; o <= 16; o <<= 1) {
                        const unsigned long long ok = __shfl_xor_sync(0xFFFFFFFFu, key, o);
                        if (ok > key) key = ok;
                    }
                    if (lane < 4) atomicMax(&g_best[gcol], key);
                }
            }

            // ---- row-side fold + accumulator reset ----
            #pragma unroll
            for (int mt = 0; mt < 4; mt++) {
                #pragma unroll
                for (int rh = 0; rh < 2; rh++) {
                    const int grow = rowb + mt * 16 + (lane >> 2) + rh * 8;
                    float bv = -2.f; int bi = 0;
                    #pragma unroll
                    for (int j = 0; j < 4; j++) {
                        const __half2 hv = *(const __half2*)&c2[mt][j][rh];
                        const float v0 = __low2float(hv);
                        const float v1 = __high2float(hv);
                        const int col0 = colb + j * 8 + (lane & 3) * 2;
                        if (col0 != grow && v0 > bv) { bv = v0; bi = col0; }
                        if (col0 + 1 != grow && v1 > bv) { bv = v1; bi = col0 + 1; }
                        c2[mt][j][rh] = 0u;
                    }
                    unsigned long long key =
                        ((unsigned long long)fenc(bv) << 32) |
                        (unsigned long long)(0xFFFFFFFFu - (uint32_t)bi);
                    #pragma unroll
                    for (int o = 1; o <= 2; o <<= 1) {
                        const unsigned long long ok = __shfl_xor_sync(0xFFFFFFFFu, key, o);
                        if (ok > key) key = ok;
                    }
                    if ((lane & 3) == 0) atomicMax(&g_best[grow], key);
                }
            }
        }
    }
}

// ---------------- kernel 3: exact fp32 distance from input + row norms ----------------
__global__ void koleo_dist_kernel(const float* __restrict__ x) {
    const int i = blockIdx.x;
    const int tid = threadIdx.x;  // 128
    const int j = (int)(0xFFFFFFFFu - (uint32_t)g_best[i]);
    const float ri = g_rnorm[i], rj = g_rnorm[j];
    const float4* a = (const float4*)(x + (size_t)i * DIMK);
    const float4* b = (const float4*)(x + (size_t)j * DIMK);
    float s = 0.f;
    #pragma unroll
    for (int t = 0; t < 2; t++) {
        const int idx = tid + t * 128;
        const float4 av = a[idx], bv = b[idx];
        const float d0 = av.x * ri - bv.x * rj + 1e-8f;
        const float d1 = av.y * ri - bv.y * rj + 1e-8f;
        const float d2 = av.z * ri - bv.z * rj + 1e-8f;
        const float d3 = av.w * ri - bv.w * rj + 1e-8f;
        s += d0 * d0 + d1 * d1 + d2 * d2 + d3 * d3;
    }
    #pragma unroll
    for (int o = 16; o; o >>= 1) s += __shfl_xor_sync(0xFFFFFFFFu, s, o);
    __shared__ float ws[4];
    if ((tid & 31) == 0) ws[tid >> 5] = s;
    __syncthreads();
    if (tid == 0) {
        const float t = ws[0] + ws[1] + ws[2] + ws[3];
        g_logd[i] = logf(sqrtf(t) + 1e-8f);
    }
}

// ---------------- kernel 4: deterministic mean reduction ----------------
__global__ void koleo_finish_kernel(float* __restrict__ out) {
    const int tid = threadIdx.x;  // 1024
    float s = 0.f;
    #pragma unroll
    for (int t = 0; t < 8; t++) s += g_logd[tid + t * 1024];
    #pragma unroll
    for (int o = 16; o; o >>= 1) s += __shfl_xor_sync(0xFFFFFFFFu, s, o);
    __shared__ float ws[32];
    if ((tid & 31) == 0) ws[tid >> 5] = s;
    __syncthreads();
    if (tid == 0) {
        float t = 0.f;
        #pragma unroll
        for (int i = 0; i < 32; i++) t += ws[i];
        out[0] = -(t / 8192.f);
    }
}

// ---------------- launch ----------------
extern "C" void kernel_launch(void* const* d_in, const int* in_sizes, int n_in,
                              void* d_out, int out_size) {
    (void)in_sizes; (void)n_in; (void)out_size;
    const float* x = (const float*)d_in[0];
    const int smem_bytes = 2 * 32768 + 64;
    cudaFuncSetAttribute(koleo_argmax_kernel, cudaFuncAttributeMaxDynamicSharedMemorySize,
                         smem_bytes);
    koleo_normalize_kernel<<<N_ROWS, 256>>>(x);
    koleo_argmax_kernel<<<NCTA3, 256, smem_bytes>>>();
    koleo_dist_kernel<<<N_ROWS, 128>>>(x);
    koleo_finish_kernel<<<1, 1024>>>((float*)d_out);
}

// round 15
// speedup vs baseline: 1.1848x; 1.0213x over previous
#include <cuda_runtime.h>
#include <cuda_fp16.h>
#include <cstdint>
#include <math.h>

#define N_ROWS 8192
#define DIMK   1024
#define NCTA3  444            // 3 CTAs per SM
#define NJOBS_T 2080          // triangle 128x128 tiles incl. diagonal: 64*65/2
#define STAGE_BYTES 32768u
#define JSENT 0xFFFFFFFFu

// ---------------- scratch (static device memory, no allocs) ----------------
__device__ __align__(16) __half g_Xh[N_ROWS * DIMK];   // 16 MB fp16 row-major
__device__ float g_rnorm[N_ROWS];                      // 1/max(||x||,eps)
__device__ unsigned long long g_best[N_ROWS];          // packed (enc(val)<<32 | ~col)
__device__ float g_logd[N_ROWS];
__device__ int   g_jobctr;                             // dynamic work queue head

// ---------------- helpers ----------------
__device__ __forceinline__ uint32_t smem_u32(const void* p) {
    uint32_t a;
    asm("{ .reg .u64 t; cvta.to.shared.u64 t, %1; cvt.u32.u64 %0, t; }" : "=r"(a) : "l"(p));
    return a;
}
__device__ __forceinline__ void cp16(uint32_t dst, const void* src) {
    asm volatile("cp.async.cg.shared.global [%0], [%1], 16;" :: "r"(dst), "l"(src));
}
__device__ __forceinline__ void ldsm4(uint32_t& r0, uint32_t& r1, uint32_t& r2, uint32_t& r3,
                                      uint32_t addr) {
    asm volatile("ldmatrix.sync.aligned.m8n8.x4.shared.b16 {%0,%1,%2,%3}, [%4];"
                 : "=r"(r0), "=r"(r1), "=r"(r2), "=r"(r3) : "r"(addr));
}
__device__ __forceinline__ void mma16816h(uint32_t* c, uint32_t a0, uint32_t a1, uint32_t a2,
                                          uint32_t a3, uint32_t b0, uint32_t b1) {
    asm volatile("mma.sync.aligned.m16n8k16.row.col.f16.f16.f16.f16 "
                 "{%0,%1}, {%2,%3,%4,%5}, {%6,%7}, {%0,%1};"
                 : "+r"(c[0]), "+r"(c[1])
                 : "r"(a0), "r"(a1), "r"(a2), "r"(a3), "r"(b0), "r"(b1));
}
// monotonic float->u32 (total order preserved, incl. negatives)
__device__ __forceinline__ uint32_t fenc(float v) {
    const uint32_t u = __float_as_uint(v);
    return (u & 0x80000000u) ? ~u : (u | 0x80000000u);
}
// job index -> (rb, cb) over the 64x64 block triangle (cb >= rb).
// Row rb has (64 - rb) jobs; cumulative S(r) = r*(129-r)/2.
__device__ __forceinline__ uint32_t job_decode(int jj) {
    int u = 0;
    #pragma unroll 1
    while ((u + 1) * (129 - (u + 1)) / 2 <= jj) u++;
    const int c = u + (jj - u * (129 - u) / 2);
    return ((uint32_t)u << 8) | (uint32_t)c;
}

// ---------------- kernel 1: warp-per-row norms + fp16 pack; resets ----------------
// 1024 blocks x 256 threads; warp w handles row blockIdx.x*8 + w. No __syncthreads.
__global__ void __launch_bounds__(256) koleo_normalize_kernel(const float* __restrict__ x) {
    const int lane = threadIdx.x & 31;
    const int row = blockIdx.x * 8 + (threadIdx.x >> 5);
    if (lane == 0) {
        g_best[row] = 0ull;
        if (row == 0) g_jobctr = 0;
    }
    const float4* xr = (const float4*)(x + (size_t)row * DIMK);
    float4 v[8];
    float ss = 0.f;
    #pragma unroll
    for (int t = 0; t < 8; t++) {
        v[t] = xr[lane + t * 32];
        ss += v[t].x * v[t].x + v[t].y * v[t].y + v[t].z * v[t].z + v[t].w * v[t].w;
    }
    #pragma unroll
    for (int o = 16; o; o >>= 1) ss += __shfl_xor_sync(0xFFFFFFFFu, ss, o);
    const float s = 1.f / fmaxf(sqrtf(ss), 1e-8f);
    if (lane == 0) g_rnorm[row] = s;
    #pragma unroll
    for (int t = 0; t < 8; t++) {
        __half2 h0 = __floats2half2_rn(v[t].x * s, v[t].y * s);
        __half2 h1 = __floats2half2_rn(v[t].z * s, v[t].w * s);
        uint2 u;
        u.x = *(const uint32_t*)&h0;
        u.y = *(const uint32_t*)&h1;
        *(uint2*)(g_Xh + (size_t)row * DIMK + (lane + t * 32) * 4) = u;
    }
}

// ---------------- kernel 2: persistent fp16 GEMM, dynamic job queue (R14, unchanged) ----
// 444 CTAs (3/SM). Jobs pulled from g_jobctr; rolling 8-entry jtab in smem.
// Tile 128x128, warp tile 64x32, K64 stages, 2 smem buffers, depth-1 prefetch.
// Stage-head reorder: kstep-0 ldmatrix issued BEFORE next-stage copy.

__device__ __forceinline__ void copy_stream(uint32_t sbase, const uint32_t* jtab,
                                            int s, int tid) {
    const uint32_t rbcb = jtab[(s >> 4) & 7];
    if (rbcb != JSENT) {
        const int rb = (int)(rbcb >> 8), cb = (int)(rbcb & 255u), kc = s & 15;
        const uint32_t dst = sbase + (uint32_t)(s & 1) * STAGE_BYTES;
        const __half* gA = g_Xh + (size_t)(rb * 128) * DIMK + kc * 64;
        const __half* gB = g_Xh + (size_t)(cb * 128) * DIMK + kc * 64;
        #pragma unroll
        for (int i = 0; i < 4; i++) {
            const int idx = tid + i * 256;
            const int r = idx >> 3, ch = idx & 7;
            const uint32_t doff = (uint32_t)r * 128u + ((uint32_t)(ch ^ (r & 7)) << 4);
            cp16(dst + doff, gA + (size_t)r * DIMK + ch * 8);
        }
        #pragma unroll
        for (int i = 0; i < 4; i++) {
            const int idx = tid + i * 256;
            const int r = idx >> 3, ch = idx & 7;
            const uint32_t doff = (uint32_t)r * 128u + ((uint32_t)(ch ^ (r & 7)) << 4);
            cp16(dst + 16384u + doff, gB + (size_t)r * DIMK + ch * 8);
        }
    }
    asm volatile("cp.async.commit_group;" ::: "memory");
}

__global__ void __launch_bounds__(256, 3) koleo_argmax_kernel() {
    extern __shared__ unsigned char smem[];
    const uint32_t sbase = smem_u32(smem);
    uint32_t* jtab = (uint32_t*)(smem + 2 * STAGE_BYTES);   // rolling ring of 8 job ids
    const int tid = threadIdx.x;
    const int lane = tid & 31;
    const int wid = tid >> 5;
    const int wm = wid & 1;        // rows [wm*64, wm*64+64)
    const int wn = wid >> 1;       // cols [wn*32, wn*32+32)

    if (tid == 0) {
        const int j0 = atomicAdd(&g_jobctr, 1);
        jtab[0] = (j0 < NJOBS_T) ? job_decode(j0) : JSENT;
    }
    __syncthreads();

    uint32_t c2[4][4][2];   // fp16x2 accumulators (warp tile 64x32)
    #pragma unroll
    for (int a = 0; a < 4; a++)
        #pragma unroll
        for (int b = 0; b < 4; b++) { c2[a][b][0] = 0u; c2[a][b][1] = 0u; }

    copy_stream(sbase, jtab, 0, tid);

    for (int s = 0;; s++) {
        asm volatile("cp.async.wait_group 0;" ::: "memory");
        __syncthreads();
        const uint32_t curj = jtab[(s >> 4) & 7];
        if (curj == JSENT) break;

        const uint32_t A = sbase + (uint32_t)(s & 1) * STAGE_BYTES;
        const uint32_t B = A + 16384u;

        // ---- kstep 0 fragment loads FIRST (fills the tensor-pipe pipeline) ----
        uint32_t bf[2][4], af[4][4];
        {
            const uint32_t kc = (uint32_t)(lane >> 4);
            #pragma unroll
            for (int nb = 0; nb < 2; nb++) {
                const uint32_t r = (uint32_t)(wn * 32 + nb * 16 + (lane & 15));
                ldsm4(bf[nb][0], bf[nb][1], bf[nb][2], bf[nb][3],
                      B + r * 128u + ((kc ^ (r & 7u)) << 4));
            }
            #pragma unroll
            for (int mt = 0; mt < 4; mt++) {
                const uint32_t r = (uint32_t)(wm * 64 + mt * 16 + (lane & 15));
                ldsm4(af[mt][0], af[mt][1], af[mt][2], af[mt][3],
                      A + r * 128u + ((kc ^ (r & 7u)) << 4));
            }
        }

        // ---- next-job fetch + next-stage copy issue in the LDSM/MMA shadow ----
        if ((s & 15) == 14 && tid == 0) {
            const int jn = atomicAdd(&g_jobctr, 1);
            jtab[((s >> 4) + 1) & 7] = (jn < NJOBS_T) ? job_decode(jn) : JSENT;
        }
        copy_stream(sbase, jtab, s + 1, tid);

        // ---- kstep 0 MMAs ----
        #pragma unroll
        for (int mt = 0; mt < 4; mt++)
            #pragma unroll
            for (int j = 0; j < 4; j++)
                mma16816h(c2[mt][j], af[mt][0], af[mt][1], af[mt][2], af[mt][3],
                          bf[j >> 1][j & 1], bf[j >> 1][2 + (j & 1)]);

        // ---- ksteps 1..3 ----
        #pragma unroll
        for (int t = 1; t < 4; t++) {
            const uint32_t kc = (uint32_t)(t << 1) + (uint32_t)(lane >> 4);
            #pragma unroll
            for (int nb = 0; nb < 2; nb++) {
                const uint32_t r = (uint32_t)(wn * 32 + nb * 16 + (lane & 15));
                ldsm4(bf[nb][0], bf[nb][1], bf[nb][2], bf[nb][3],
                      B + r * 128u + ((kc ^ (r & 7u)) << 4));
            }
            #pragma unroll
            for (int mt = 0; mt < 4; mt++) {
                const uint32_t r = (uint32_t)(wm * 64 + mt * 16 + (lane & 15));
                ldsm4(af[mt][0], af[mt][1], af[mt][2], af[mt][3],
                      A + r * 128u + ((kc ^ (r & 7u)) << 4));
            }
            #pragma unroll
            for (int mt = 0; mt < 4; mt++)
                #pragma unroll
                for (int j = 0; j < 4; j++)
                    mma16816h(c2[mt][j], af[mt][0], af[mt][1], af[mt][2], af[mt][3],
                              bf[j >> 1][j & 1], bf[j >> 1][2 + (j & 1)]);
        }

        if ((s & 15) == 15) {
            const int rb = (int)(curj >> 8), cb = (int)(curj & 255u);
            const int colb = cb * 128 + wn * 32;
            const int rowb = rb * 128 + wm * 64;

            // ---- column-side fold (symmetry): per-column max over 128 rows ----
            #pragma unroll
            for (int j = 0; j < 4; j++) {
                #pragma unroll
                for (int h = 0; h < 2; h++) {
                    const int gcol = colb + j * 8 + (lane & 3) * 2 + h;
                    float cv = -2.f; int cr = 0;
                    #pragma unroll
                    for (int mt = 0; mt < 4; mt++) {
                        #pragma unroll
                        for (int rh = 0; rh < 2; rh++) {
                            const __half2 hv = *(const __half2*)&c2[mt][j][rh];
                            const float v = h ? __high2float(hv) : __low2float(hv);
                            const int grow = rowb + mt * 16 + (lane >> 2) + rh * 8;
                            if (grow != gcol && (v > cv || (v == cv && grow < cr))) {
                                cv = v; cr = grow;
                            }
                        }
                    }
                    unsigned long long key =
                        ((unsigned long long)fenc(cv) << 32) |
                        (unsigned long long)(0xFFFFFFFFu - (uint32_t)cr);
                    #pragma unroll
                    for (int o = 4; o <= 16; o <<= 1) {
                        const unsigned long long ok = __shfl_xor_sync(0xFFFFFFFFu, key, o);
                        if (ok > key) key = ok;
                    }
                    if (lane < 4) atomicMax(&g_best[gcol], key);
                }
            }

            // ---- row-side fold + accumulator reset ----
            #pragma unroll
            for (int mt = 0; mt < 4; mt++) {
                #pragma unroll
                for (int rh = 0; rh < 2; rh++) {
                    const int grow = rowb + mt * 16 + (lane >> 2) + rh * 8;
                    float bv = -2.f; int bi = 0;
                    #pragma unroll
                    for (int j = 0; j < 4; j++) {
                        const __half2 hv = *(const __half2*)&c2[mt][j][rh];
                        const float v0 = __low2float(hv);
                        const float v1 = __high2float(hv);
                        const int col0 = colb + j * 8 + (lane & 3) * 2;
                        if (col0 != grow && v0 > bv) { bv = v0; bi = col0; }
                        if (col0 + 1 != grow && v1 > bv) { bv = v1; bi = col0 + 1; }
                        c2[mt][j][rh] = 0u;
                    }
                    unsigned long long key =
                        ((unsigned long long)fenc(bv) << 32) |
                        (unsigned long long)(0xFFFFFFFFu - (uint32_t)bi);
                    #pragma unroll
                    for (int o = 1; o <= 2; o <<= 1) {
                        const unsigned long long ok = __shfl_xor_sync(0xFFFFFFFFu, key, o);
                        if (ok > key) key = ok;
                    }
                    if ((lane & 3) == 0) atomicMax(&g_best[grow], key);
                }
            }
        }
    }
}

// ---------------- kernel 3: warp-per-row exact fp32 distance ----------------
// 1024 blocks x 256 threads; warp w handles row blockIdx.x*8 + w. No __syncthreads.
__global__ void __launch_bounds__(256) koleo_dist_kernel(const float* __restrict__ x) {
    const int lane = threadIdx.x & 31;
    const int i = blockIdx.x * 8 + (threadIdx.x >> 5);
    const int j = (int)(0xFFFFFFFFu - (uint32_t)g_best[i]);
    const float ri = g_rnorm[i], rj = g_rnorm[j];
    const float4* a = (const float4*)(x + (size_t)i * DIMK);
    const float4* b = (const float4*)(x + (size_t)j * DIMK);
    float s = 0.f;
    #pragma unroll
    for (int t = 0; t < 8; t++) {
        const int idx = lane + t * 32;
        const float4 av = a[idx], bv = b[idx];
        const float d0 = av.x * ri - bv.x * rj + 1e-8f;
        const float d1 = av.y * ri - bv.y * rj + 1e-8f;
        const float d2 = av.z * ri - bv.z * rj + 1e-8f;
        const float d3 = av.w * ri - bv.w * rj + 1e-8f;
        s += d0 * d0 + d1 * d1 + d2 * d2 + d3 * d3;
    }
    #pragma unroll
    for (int o = 16; o; o >>= 1) s += __shfl_xor_sync(0xFFFFFFFFu, s, o);
    if (lane == 0) g_logd[i] = logf(sqrtf(s) + 1e-8f);
}

// ---------------- kernel 4: deterministic mean reduction (unchanged) ----------------
__global__ void koleo_finish_kernel(float* __restrict__ out) {
    const int tid = threadIdx.x;  // 1024
    float s = 0.f;
    #pragma unroll
    for (int t = 0; t < 8; t++) s += g_logd[tid + t * 1024];
    #pragma unroll
    for (int o = 16; o; o >>= 1) s += __shfl_xor_sync(0xFFFFFFFFu, s, o);
    __shared__ float ws[32];
    if ((tid & 31) == 0) ws[tid >> 5] = s;
    __syncthreads();
    if (tid == 0) {
        float t = 0.f;
        #pragma unroll
        for (int i = 0; i < 32; i++) t += ws[i];
        out[0] = -(t / 8192.f);
    }
}

// ---------------- launch ----------------
extern "C" void kernel_launch(void* const* d_in, const int* in_sizes, int n_in,
                              void* d_out, int out_size) {
    (void)in_sizes; (void)n_in; (void)out_size;
    const float* x = (const float*)d_in[0];
    const int smem_bytes = 2 * 32768 + 64;
    cudaFuncSetAttribute(koleo_argmax_kernel, cudaFuncAttributeMaxDynamicSharedMemorySize,
                         smem_bytes);
    koleo_normalize_kernel<<<N_ROWS / 8, 256>>>(x);
    koleo_argmax_kernel<<<NCTA3, 256, smem_bytes>>>();
    koleo_dist_kernel<<<N_ROWS / 8, 256>>>(x);
    koleo_finish_kernel<<<1, 1024>>>((float*)d_out);
}